// round 6
// baseline (speedup 1.0000x reference)
#include <cuda_runtime.h>
#include <cstdint>

#define B_   2
#define SQ_  2048
#define SK_  2048
#define D_   1024
#define H_   16
#define DK_  64

// Scratch (allocation-free: static device globals)
__device__ float g_q[(size_t)B_ * H_ * SQ_ * DK_];   // [B,H,SQ,DK]
__device__ float g_k[(size_t)B_ * H_ * SK_ * DK_];   // [B,H,SK,DK]
__device__ float g_v[(size_t)B_ * H_ * SK_ * DK_];   // [B,H,SK,DK]
__device__ float g_ctx[(size_t)B_ * SQ_ * D_];       // [B,SQ,D]

__device__ __forceinline__ float neg_inf() { return __int_as_float(0xff800000); }

// ---------------------------------------------------------------------------
// Y = X @ W^T  with X:[M,K] row-major, W:[N,K] row-major.
// M = B*S = 4096, N = K = 1024 (all fixed, all tile-divisible).
// MODE 0: Y row-major [M,N].
// MODE 1: Y scattered to [B, H, S, DK] (head split + transpose fused).
// 128x128 C-tile, BK=16, 256 threads, 8x8 per-thread in split 4+4 fragments.
// ---------------------------------------------------------------------------
template <int MODE>
__global__ __launch_bounds__(256) void gemm_xwt(const float* __restrict__ X,
                                                const float* __restrict__ W,
                                                float* __restrict__ Y) {
    const int K = D_;
    const int N = D_;
    __shared__ __align__(16) float As[16][132];
    __shared__ __align__(16) float Bs[16][132];

    const int tid = threadIdx.x;
    const int tx = tid & 15;
    const int ty = tid >> 4;
    const int m0 = blockIdx.y * 128;
    const int n0 = blockIdx.x * 128;

    float acc[8][8];
#pragma unroll
    for (int i = 0; i < 8; i++)
#pragma unroll
        for (int j = 0; j < 8; j++) acc[i][j] = 0.f;

    for (int k0 = 0; k0 < K; k0 += 16) {
#pragma unroll
        for (int s = 0; s < 2; s++) {
            int slot = tid + s * 256;            // 0..511
            int r    = slot >> 2;                // 0..127
            int c4   = (slot & 3) * 4;           // 0,4,8,12
            float4 va = *reinterpret_cast<const float4*>(&X[(size_t)(m0 + r) * K + k0 + c4]);
            As[c4 + 0][r] = va.x; As[c4 + 1][r] = va.y;
            As[c4 + 2][r] = va.z; As[c4 + 3][r] = va.w;
            float4 vb = *reinterpret_cast<const float4*>(&W[(size_t)(n0 + r) * K + k0 + c4]);
            Bs[c4 + 0][r] = vb.x; Bs[c4 + 1][r] = vb.y;
            Bs[c4 + 2][r] = vb.z; Bs[c4 + 3][r] = vb.w;
        }
        __syncthreads();

#pragma unroll
        for (int kk = 0; kk < 16; kk++) {
            float4 a0 = *reinterpret_cast<const float4*>(&As[kk][ty * 4]);
            float4 a1 = *reinterpret_cast<const float4*>(&As[kk][64 + ty * 4]);
            float4 b0 = *reinterpret_cast<const float4*>(&Bs[kk][tx * 4]);
            float4 b1 = *reinterpret_cast<const float4*>(&Bs[kk][64 + tx * 4]);
            float a[8] = {a0.x, a0.y, a0.z, a0.w, a1.x, a1.y, a1.z, a1.w};
            float b[8] = {b0.x, b0.y, b0.z, b0.w, b1.x, b1.y, b1.z, b1.w};
#pragma unroll
            for (int i = 0; i < 8; i++)
#pragma unroll
                for (int j = 0; j < 8; j++)
                    acc[i][j] = fmaf(a[i], b[j], acc[i][j]);
        }
        __syncthreads();
    }

#pragma unroll
    for (int i = 0; i < 8; i++) {
        int row = (i < 4) ? (ty * 4 + i) : (64 + ty * 4 + (i - 4));
        int m = m0 + row;
#pragma unroll
        for (int jg = 0; jg < 2; jg++) {
            int col = jg ? (64 + tx * 4) : (tx * 4);
            float4 v = make_float4(acc[i][jg * 4 + 0], acc[i][jg * 4 + 1],
                                   acc[i][jg * 4 + 2], acc[i][jg * 4 + 3]);
            int n = n0 + col;
            if (MODE == 0) {
                *reinterpret_cast<float4*>(&Y[(size_t)m * N + n]) = v;
            } else {
                int h  = n >> 6;       // n / DK
                int dk = n & 63;       // n % DK  (group of 4 stays inside one head)
                int b  = m >> 11;      // m / 2048
                int s  = m & 2047;     // m % 2048
                *reinterpret_cast<float4*>(
                    &Y[(((size_t)(b * H_ + h)) * SQ_ + s) * DK_ + dk]) = v;
            }
        }
    }
}

// ---------------------------------------------------------------------------
// Flash attention, fp32, causal + padding mask.
// One block per (64-query tile, b*h). 256 threads (16x16), 4x4 per thread.
// Smem: Qst/Kst [dk][q|k] (transposed, pad 68), Vs [k][dk], Ps [q][k].
// ---------------------------------------------------------------------------
__global__ __launch_bounds__(256) void attn_fwd(const float* __restrict__ Qp,
                                                const float* __restrict__ Kp,
                                                const float* __restrict__ Vp,
                                                const int* __restrict__ mask,
                                                float* __restrict__ ctx) {
    extern __shared__ float sm[];
    float* Qst = sm;                   // [64][68]  (dk-major)
    float* Kst = Qst + 64 * 68;        // [64][68]  (dk-major)
    float* Vs  = Kst + 64 * 68;        // [64][68]  (key-major)
    float* Ps  = Vs  + 64 * 68;        // [64][68]  (query-major)
    int*   mS  = (int*)(Ps + 64 * 68); // [64]

    const int tid = threadIdx.x;
    const int tx = tid & 15;
    const int ty = tid >> 4;
    const int qt0 = blockIdx.x * 64;
    const int bh  = blockIdx.y;
    const int b   = bh >> 4;
    const int h   = bh & 15;

    const float* Qb = Qp + (size_t)bh * SQ_ * DK_;
    const float* Kb = Kp + (size_t)bh * SK_ * DK_;
    const float* Vb = Vp + (size_t)bh * SK_ * DK_;
    const int*   mb = mask + b * SK_;

    // Load Q tile transposed into Qst[dk][q]
#pragma unroll
    for (int s = 0; s < 4; s++) {
        int slot = tid + s * 256;          // 0..1023
        int r  = slot >> 4;                // query row 0..63
        int c4 = (slot & 15) * 4;          // dk
        float4 v = *reinterpret_cast<const float4*>(&Qb[(size_t)(qt0 + r) * DK_ + c4]);
        Qst[(c4 + 0) * 68 + r] = v.x; Qst[(c4 + 1) * 68 + r] = v.y;
        Qst[(c4 + 2) * 68 + r] = v.z; Qst[(c4 + 3) * 68 + r] = v.w;
    }

    float m_i[4], l_i[4], o[4][4];
#pragma unroll
    for (int i = 0; i < 4; i++) {
        m_i[i] = neg_inf();
        l_i[i] = 0.f;
#pragma unroll
        for (int j = 0; j < 4; j++) o[i][j] = 0.f;
    }

    const int ktMax = qt0 >> 6;
    for (int kt = 0; kt <= ktMax; kt++) {
        const int kt0 = kt * 64;
        // Padding mask is a monotone prefix (arange < length): first key
        // invalid => whole tile and all later tiles invalid. Uniform read.
        if (mb[kt0] == 0) break;

        __syncthreads();   // prior iteration done reading Vs/Ps/Kst
        if (tid < 64) mS[tid] = mb[kt0 + tid];
#pragma unroll
        for (int s = 0; s < 4; s++) {
            int slot = tid + s * 256;
            int r  = slot >> 4;
            int c4 = (slot & 15) * 4;
            float4 kv = *reinterpret_cast<const float4*>(&Kb[(size_t)(kt0 + r) * DK_ + c4]);
            Kst[(c4 + 0) * 68 + r] = kv.x; Kst[(c4 + 1) * 68 + r] = kv.y;
            Kst[(c4 + 2) * 68 + r] = kv.z; Kst[(c4 + 3) * 68 + r] = kv.w;
            float4 vv = *reinterpret_cast<const float4*>(&Vb[(size_t)(kt0 + r) * DK_ + c4]);
            *reinterpret_cast<float4*>(&Vs[r * 68 + c4]) = vv;
        }
        __syncthreads();

        // S = Q . K^T  (4x4 per thread)
        float s4[4][4];
#pragma unroll
        for (int i = 0; i < 4; i++)
#pragma unroll
            for (int j = 0; j < 4; j++) s4[i][j] = 0.f;

#pragma unroll 16
        for (int kk = 0; kk < 64; kk++) {
            float4 qf = *reinterpret_cast<const float4*>(&Qst[kk * 68 + ty * 4]);
            float4 kf = *reinterpret_cast<const float4*>(&Kst[kk * 68 + tx * 4]);
            float qa[4] = {qf.x, qf.y, qf.z, qf.w};
            float ka[4] = {kf.x, kf.y, kf.z, kf.w};
#pragma unroll
            for (int i = 0; i < 4; i++)
#pragma unroll
                for (int j = 0; j < 4; j++)
                    s4[i][j] = fmaf(qa[i], ka[j], s4[i][j]);
        }

        // mask + scale + online softmax (row stats replicated across tx via
        // width-16 butterflies; tx lanes stay inside their 16-lane group)
#pragma unroll
        for (int i = 0; i < 4; i++) {
            int qg = qt0 + ty * 4 + i;
            float mt = neg_inf();
#pragma unroll
            for (int j = 0; j < 4; j++) {
                int kg = kt0 + tx * 4 + j;
                float v = s4[i][j] * 0.125f;  // 1/sqrt(DK)
                if (kg > qg || mS[tx * 4 + j] == 0) v = neg_inf();
                s4[i][j] = v;
                mt = fmaxf(mt, v);
            }
#pragma unroll
            for (int off = 8; off; off >>= 1)
                mt = fmaxf(mt, __shfl_xor_sync(0xffffffffu, mt, off));
            // Every processed tile has key kt0 valid for every row in this
            // q-tile (kt0 <= qt0 <= qg, mask[kt0]!=0) => mt is finite.
            float mnew  = fmaxf(m_i[i], mt);
            float alpha = __expf(m_i[i] - mnew);   // exp(-inf)=0 on first tile
            m_i[i] = mnew;
            float rs = 0.f;
#pragma unroll
            for (int j = 0; j < 4; j++) {
                float p = __expf(s4[i][j] - mnew);
                s4[i][j] = p;
                rs += p;
            }
#pragma unroll
            for (int off = 8; off; off >>= 1)
                rs += __shfl_xor_sync(0xffffffffu, rs, off);
            l_i[i] = l_i[i] * alpha + rs;
#pragma unroll
            for (int j = 0; j < 4; j++) o[i][j] *= alpha;
            *reinterpret_cast<float4*>(&Ps[(ty * 4 + i) * 68 + tx * 4]) =
                make_float4(s4[i][0], s4[i][1], s4[i][2], s4[i][3]);
        }
        __syncthreads();

        // O += P . V
#pragma unroll
        for (int k4 = 0; k4 < 16; k4++) {
            float4 vf0 = *reinterpret_cast<const float4*>(&Vs[(k4 * 4 + 0) * 68 + tx * 4]);
            float4 vf1 = *reinterpret_cast<const float4*>(&Vs[(k4 * 4 + 1) * 68 + tx * 4]);
            float4 vf2 = *reinterpret_cast<const float4*>(&Vs[(k4 * 4 + 2) * 68 + tx * 4]);
            float4 vf3 = *reinterpret_cast<const float4*>(&Vs[(k4 * 4 + 3) * 68 + tx * 4]);
#pragma unroll
            for (int i = 0; i < 4; i++) {
                float4 pf = *reinterpret_cast<const float4*>(&Ps[(ty * 4 + i) * 68 + k4 * 4]);
                o[i][0] += pf.x * vf0.x + pf.y * vf1.x + pf.z * vf2.x + pf.w * vf3.x;
                o[i][1] += pf.x * vf0.y + pf.y * vf1.y + pf.z * vf2.y + pf.w * vf3.y;
                o[i][2] += pf.x * vf0.z + pf.y * vf1.z + pf.z * vf2.z + pf.w * vf3.z;
                o[i][3] += pf.x * vf0.w + pf.y * vf1.w + pf.z * vf2.w + pf.w * vf3.w;
            }
        }
    }

    // Epilogue: ctx[b, q, h*DK + d] = o / l   (l >= 1: key 0 always valid)
#pragma unroll
    for (int i = 0; i < 4; i++) {
        float inv = 1.0f / l_i[i];
        int qg = qt0 + ty * 4 + i;
        float4 out = make_float4(o[i][0] * inv, o[i][1] * inv,
                                 o[i][2] * inv, o[i][3] * inv);
        *reinterpret_cast<float4*>(
            &ctx[((size_t)(b * SQ_) + qg) * D_ + h * DK_ + tx * 4]) = out;
    }
}

static const int ATTN_SMEM = (4 * 64 * 68) * (int)sizeof(float) + 64 * (int)sizeof(int);

extern "C" void kernel_launch(void* const* d_in, const int* in_sizes, int n_in,
                              void* d_out, int out_size) {
    const float* query = (const float*)d_in[0];
    const float* keyi  = (const float*)d_in[1];
    const float* value = (const float*)d_in[2];
    const int*   mask  = (const int*)d_in[3];
    const float* Wq    = (const float*)d_in[4];
    const float* Wk    = (const float*)d_in[5];
    const float* Wv    = (const float*)d_in[6];
    const float* Wo    = (const float*)d_in[7];
    float* out = (float*)d_out;

    float *qb, *kb, *vb, *cb;
    cudaGetSymbolAddress((void**)&qb, g_q);
    cudaGetSymbolAddress((void**)&kb, g_k);
    cudaGetSymbolAddress((void**)&vb, g_v);
    cudaGetSymbolAddress((void**)&cb, g_ctx);

    cudaFuncSetAttribute(attn_fwd, cudaFuncAttributeMaxDynamicSharedMemorySize,
                         ATTN_SMEM);

    dim3 gg(D_ / 128, (B_ * SQ_) / 128);  // (8, 32)
    gemm_xwt<1><<<gg, 256>>>(query, Wq, qb);
    gemm_xwt<1><<<gg, 256>>>(keyi,  Wk, kb);
    gemm_xwt<1><<<gg, 256>>>(value, Wv, vb);
    attn_fwd<<<dim3(SQ_ / 64, B_ * H_), 256, ATTN_SMEM>>>(qb, kb, vb, mask, cb);
    gemm_xwt<0><<<gg, 256>>>(cb, Wo, out);
}

// round 13
// speedup vs baseline: 1.3030x; 1.3030x over previous
#include <cuda_runtime.h>
#include <cuda_bf16.h>
#include <cstdint>

#define B_   2
#define SQ_  2048
#define SK_  2048
#define D_   1024
#define H_   16
#define DK_  64

// ---------------------------------------------------------------------------
// Scratch (allocation-free: static device globals)
// ---------------------------------------------------------------------------
__device__ float g_q[(size_t)B_ * H_ * SQ_ * DK_];   // [B,H,SQ,DK]
__device__ float g_k[(size_t)B_ * H_ * SK_ * DK_];   // [B,H,SK,DK]
__device__ float g_v[(size_t)B_ * H_ * SK_ * DK_];   // [B,H,SK,DK]
__device__ float g_ctx[(size_t)B_ * SQ_ * D_];       // [B,SQ,D]

// split-bf16 staging buffers (reused sequentially across the 4 GEMMs)
__device__ __align__(16) __nv_bfloat16 g_xhi[(size_t)4096 * 1024];
__device__ __align__(16) __nv_bfloat16 g_xlo[(size_t)4096 * 1024];
__device__ __align__(16) __nv_bfloat16 g_whi[(size_t)1024 * 1024];
__device__ __align__(16) __nv_bfloat16 g_wlo[(size_t)1024 * 1024];

__device__ __forceinline__ float neg_inf() { return __int_as_float(0xff800000); }

__device__ __forceinline__ uint32_t smem_u32(const void* p) {
    uint32_t a;
    asm("{ .reg .u64 t; cvta.to.shared.u64 t, %1; cvt.u32.u64 %0, t; }"
        : "=r"(a) : "l"(p));
    return a;
}

// plain (non-transposed) ldmatrix x4 — correct for BOTH A[m][k] and W[n][k]
// since both are k-contiguous and the mma fragments want k-pairs.
__device__ __forceinline__ void ldm_x4(uint32_t* r, uint32_t addr) {
    asm volatile(
        "ldmatrix.sync.aligned.m8n8.x4.shared.b16 {%0,%1,%2,%3}, [%4];"
        : "=r"(r[0]), "=r"(r[1]), "=r"(r[2]), "=r"(r[3]) : "r"(addr));
}

__device__ __forceinline__ void mma_bf16(float* c, const uint32_t* a,
                                         uint32_t b0, uint32_t b1) {
    asm volatile(
        "mma.sync.aligned.m16n8k16.row.col.f32.bf16.bf16.f32 "
        "{%0,%1,%2,%3}, {%4,%5,%6,%7}, {%8,%9}, {%0,%1,%2,%3};"
        : "+f"(c[0]), "+f"(c[1]), "+f"(c[2]), "+f"(c[3])
        : "r"(a[0]), "r"(a[1]), "r"(a[2]), "r"(a[3]), "r"(b0), "r"(b1));
}

// ---------------------------------------------------------------------------
// fp32 -> (hi, lo) bf16 split.  x = hi + lo with |x - hi - lo| ~ 2^-17 |x|.
// ---------------------------------------------------------------------------
__global__ void cvt_split(const float* __restrict__ x,
                          __nv_bfloat16* __restrict__ hi,
                          __nv_bfloat16* __restrict__ lo, int n4) {
    int i = blockIdx.x * blockDim.x + threadIdx.x;
    int stride = gridDim.x * blockDim.x;
    for (; i < n4; i += stride) {
        float4 v = reinterpret_cast<const float4*>(x)[i];
        __nv_bfloat16 hx = __float2bfloat16(v.x);
        __nv_bfloat16 hy = __float2bfloat16(v.y);
        __nv_bfloat16 hz = __float2bfloat16(v.z);
        __nv_bfloat16 hw = __float2bfloat16(v.w);
        __nv_bfloat162* hp = reinterpret_cast<__nv_bfloat162*>(hi + (size_t)i * 4);
        hp[0] = __halves2bfloat162(hx, hy);
        hp[1] = __halves2bfloat162(hz, hw);
        float lx = v.x - __bfloat162float(hx);
        float ly = v.y - __bfloat162float(hy);
        float lz = v.z - __bfloat162float(hz);
        float lw = v.w - __bfloat162float(hw);
        __nv_bfloat162* lp = reinterpret_cast<__nv_bfloat162*>(lo + (size_t)i * 4);
        lp[0] = __halves2bfloat162(__float2bfloat16(lx), __float2bfloat16(ly));
        lp[1] = __halves2bfloat162(__float2bfloat16(lz), __float2bfloat16(lw));
    }
}

// ---------------------------------------------------------------------------
// split-bf16 MMA GEMM:  Y[M,N] = X[M,K] @ W[N,K]^T, M=4096, N=K=1024.
// 128x128 CTA tile, BK=32, double-buffered smem, 8 warps (64x32 warp tiles),
// mma.sync.m16n8k16 bf16 with fp32 accumulators.
// Per k16 step: 3 products (hi*hi, hi*lo, lo*hi) x 16 mma-tiles = 48 mma/warp.
// MODE 0: Y row-major.  MODE 1: Y scattered to [B,H,S,DK].
// ---------------------------------------------------------------------------
static constexpr int GS_ROW  = 40;                       // bf16 per smem row (32+8 pad)
static constexpr int GS_ARR  = 128 * GS_ROW * 2;         // 10240 B per operand tile
static constexpr int GS_BUF  = 4 * GS_ARR;               // Ahi,Alo,Bhi,Blo = 40960 B
static constexpr int GS_SMEM = 2 * GS_BUF;               // 81920 B

template <int MODE>
__global__ __launch_bounds__(256) void gemm_mma(const __nv_bfloat16* __restrict__ Ahi,
                                                const __nv_bfloat16* __restrict__ Alo,
                                                const __nv_bfloat16* __restrict__ Bhi,
                                                const __nv_bfloat16* __restrict__ Blo,
                                                float* __restrict__ Y) {
    extern __shared__ __align__(16) char sm[];
    const uint32_t sbase = smem_u32(sm);
    const int tid  = threadIdx.x;
    const int wid  = tid >> 5;
    const int lane = tid & 31;
    const int m0 = blockIdx.y * 128;
    const int n0 = blockIdx.x * 128;
    const int K  = 1024;

    const int wy = wid & 1;        // m half (0..1) -> 64 rows
    const int wx = wid >> 1;       // n quarter (0..3) -> 32 cols

    float c[4][4][4];
#pragma unroll
    for (int mt = 0; mt < 4; mt++)
#pragma unroll
        for (int nt = 0; nt < 4; nt++)
#pragma unroll
            for (int e = 0; e < 4; e++) c[mt][nt][e] = 0.f;

    // Fill one double-buffer slot with the 4 operand tiles at k0.
    auto load_buf = [&](int kt, int buf) {
        const int k0 = kt * 32;
        const char* srcs[4] = {(const char*)Ahi, (const char*)Alo,
                               (const char*)Bhi, (const char*)Blo};
#pragma unroll
        for (int a = 0; a < 4; a++) {
            const __nv_bfloat16* src = (const __nv_bfloat16*)srcs[a];
            const int row0 = (a < 2) ? m0 : n0;
            char* dst = sm + buf * GS_BUF + a * GS_ARR;
#pragma unroll
            for (int s = 0; s < 2; s++) {
                int idx = tid + s * 256;       // 0..511
                int r = idx >> 2;              // row 0..127
                int cc = idx & 3;              // 16B chunk (4 per 32-col row)
                uint4 v = *reinterpret_cast<const uint4*>(
                    &src[(size_t)(row0 + r) * K + k0 + cc * 8]);
                *reinterpret_cast<uint4*>(dst + r * (GS_ROW * 2) + cc * 16) = v;
            }
        }
    };

    load_buf(0, 0);
    __syncthreads();

    // ldmatrix lane addressing (identical formula for A and B, non-trans):
    // row = base + (lane & 15), col = ks + (lane >> 4) * 8
    const int lrow = lane & 15;
    const int lcol = (lane >> 4) * 8;

    const int NT = K / 32;  // 32
    for (int kt = 0; kt < NT; kt++) {
        const int buf = kt & 1;
        if (kt + 1 < NT) load_buf(kt + 1, buf ^ 1);  // overlaps mma below

        const uint32_t bufb = sbase + buf * GS_BUF;
        const uint32_t aoff_hi = bufb;
        const uint32_t aoff_lo = bufb + GS_ARR;
        const uint32_t boff_hi = bufb + 2 * GS_ARR;
        const uint32_t boff_lo = bufb + 3 * GS_ARR;

#pragma unroll
        for (int ks = 0; ks < 32; ks += 16) {
            uint32_t ahi[4][4], alo[4][4], bh[2][4], bl[2][4];
#pragma unroll
            for (int p = 0; p < 2; p++) {
                uint32_t off =
                    (uint32_t)((wx * 32 + p * 16 + lrow) * GS_ROW + ks + lcol) * 2;
                ldm_x4(bh[p], boff_hi + off);
                ldm_x4(bl[p], boff_lo + off);
            }
#pragma unroll
            for (int mt = 0; mt < 4; mt++) {
                uint32_t off =
                    (uint32_t)((wy * 64 + mt * 16 + lrow) * GS_ROW + ks + lcol) * 2;
                ldm_x4(ahi[mt], aoff_hi + off);
                ldm_x4(alo[mt], aoff_lo + off);
            }
            // b-fragments from x4 result: R0=b0(nt even), R1=b0(nt odd),
            //                             R2=b1(nt even), R3=b1(nt odd)
#pragma unroll
            for (int mt = 0; mt < 4; mt++)
#pragma unroll
                for (int nt = 0; nt < 4; nt++) {
                    int p = nt >> 1, sel = nt & 1;
                    mma_bf16(c[mt][nt], ahi[mt], bh[p][sel], bh[p][sel + 2]);
                }
#pragma unroll
            for (int mt = 0; mt < 4; mt++)
#pragma unroll
                for (int nt = 0; nt < 4; nt++) {
                    int p = nt >> 1, sel = nt & 1;
                    mma_bf16(c[mt][nt], ahi[mt], bl[p][sel], bl[p][sel + 2]);
                }
#pragma unroll
            for (int mt = 0; mt < 4; mt++)
#pragma unroll
                for (int nt = 0; nt < 4; nt++) {
                    int p = nt >> 1, sel = nt & 1;
                    mma_bf16(c[mt][nt], alo[mt], bh[p][sel], bh[p][sel + 2]);
                }
        }
        __syncthreads();
    }

    // Epilogue: c0,c1 at (row = lane>>2, col = (lane&3)*2); c2,c3 at row+8.
#pragma unroll
    for (int mt = 0; mt < 4; mt++) {
#pragma unroll
        for (int nt = 0; nt < 4; nt++) {
            int row = m0 + wy * 64 + mt * 16 + (lane >> 2);
            int col = n0 + wx * 32 + nt * 8 + (lane & 3) * 2;
#pragma unroll
            for (int half = 0; half < 2; half++) {
                int m = row + half * 8;
                float2 v = make_float2(c[mt][nt][half * 2 + 0],
                                       c[mt][nt][half * 2 + 1]);
                if (MODE == 0) {
                    *reinterpret_cast<float2*>(&Y[(size_t)m * 1024 + col]) = v;
                } else {
                    int h  = col >> 6;
                    int dk = col & 63;
                    int b  = m >> 11;
                    int s  = m & 2047;
                    *reinterpret_cast<float2*>(
                        &Y[(((size_t)(b * H_ + h)) * SQ_ + s) * DK_ + dk]) = v;
                }
            }
        }
    }
}

// ---------------------------------------------------------------------------
// Flash attention, fp32, causal + padding mask (unchanged from R6 best).
// ---------------------------------------------------------------------------
__global__ __launch_bounds__(256) void attn_fwd(const float* __restrict__ Qp,
                                                const float* __restrict__ Kp,
                                                const float* __restrict__ Vp,
                                                const int* __restrict__ mask,
                                                float* __restrict__ ctx) {
    extern __shared__ float smf[];
    float* Qst = smf;
    float* Kst = Qst + 64 * 68;
    float* Vs  = Kst + 64 * 68;
    float* Ps  = Vs  + 64 * 68;
    int*   mS  = (int*)(Ps + 64 * 68);

    const int tid = threadIdx.x;
    const int tx = tid & 15;
    const int ty = tid >> 4;
    const int qt0 = blockIdx.x * 64;
    const int bh  = blockIdx.y;
    const int b   = bh >> 4;
    const int h   = bh & 15;

    const float* Qb = Qp + (size_t)bh * SQ_ * DK_;
    const float* Kb = Kp + (size_t)bh * SK_ * DK_;
    const float* Vb = Vp + (size_t)bh * SK_ * DK_;
    const int*   mb = mask + b * SK_;

#pragma unroll
    for (int s = 0; s < 4; s++) {
        int slot = tid + s * 256;
        int r  = slot >> 4;
        int c4 = (slot & 15) * 4;
        float4 v = *reinterpret_cast<const float4*>(&Qb[(size_t)(qt0 + r) * DK_ + c4]);
        Qst[(c4 + 0) * 68 + r] = v.x; Qst[(c4 + 1) * 68 + r] = v.y;
        Qst[(c4 + 2) * 68 + r] = v.z; Qst[(c4 + 3) * 68 + r] = v.w;
    }

    float m_i[4], l_i[4], o[4][4];
#pragma unroll
    for (int i = 0; i < 4; i++) {
        m_i[i] = neg_inf();
        l_i[i] = 0.f;
#pragma unroll
        for (int j = 0; j < 4; j++) o[i][j] = 0.f;
    }

    const int ktMax = qt0 >> 6;
    for (int kt = 0; kt <= ktMax; kt++) {
        const int kt0 = kt * 64;
        if (mb[kt0] == 0) break;

        __syncthreads();
        if (tid < 64) mS[tid] = mb[kt0 + tid];
#pragma unroll
        for (int s = 0; s < 4; s++) {
            int slot = tid + s * 256;
            int r  = slot >> 4;
            int c4 = (slot & 15) * 4;
            float4 kv = *reinterpret_cast<const float4*>(&Kb[(size_t)(kt0 + r) * DK_ + c4]);
            Kst[(c4 + 0) * 68 + r] = kv.x; Kst[(c4 + 1) * 68 + r] = kv.y;
            Kst[(c4 + 2) * 68 + r] = kv.z; Kst[(c4 + 3) * 68 + r] = kv.w;
            float4 vv = *reinterpret_cast<const float4*>(&Vb[(size_t)(kt0 + r) * DK_ + c4]);
            *reinterpret_cast<float4*>(&Vs[r * 68 + c4]) = vv;
        }
        __syncthreads();

        float s4[4][4];
#pragma unroll
        for (int i = 0; i < 4; i++)
#pragma unroll
            for (int j = 0; j < 4; j++) s4[i][j] = 0.f;

#pragma unroll 16
        for (int kk = 0; kk < 64; kk++) {
            float4 qf = *reinterpret_cast<const float4*>(&Qst[kk * 68 + ty * 4]);
            float4 kf = *reinterpret_cast<const float4*>(&Kst[kk * 68 + tx * 4]);
            float qa[4] = {qf.x, qf.y, qf.z, qf.w};
            float ka[4] = {kf.x, kf.y, kf.z, kf.w};
#pragma unroll
            for (int i = 0; i < 4; i++)
#pragma unroll
                for (int j = 0; j < 4; j++)
                    s4[i][j] = fmaf(qa[i], ka[j], s4[i][j]);
        }

#pragma unroll
        for (int i = 0; i < 4; i++) {
            int qg = qt0 + ty * 4 + i;
            float mt = neg_inf();
#pragma unroll
            for (int j = 0; j < 4; j++) {
                int kg = kt0 + tx * 4 + j;
                float v = s4[i][j] * 0.125f;
                if (kg > qg || mS[tx * 4 + j] == 0) v = neg_inf();
                s4[i][j] = v;
                mt = fmaxf(mt, v);
            }
#pragma unroll
            for (int off = 8; off; off >>= 1)
                mt = fmaxf(mt, __shfl_xor_sync(0xffffffffu, mt, off));
            float mnew  = fmaxf(m_i[i], mt);
            float alpha = __expf(m_i[i] - mnew);
            m_i[i] = mnew;
            float rs = 0.f;
#pragma unroll
            for (int j = 0; j < 4; j++) {
                float p = __expf(s4[i][j] - mnew);
                s4[i][j] = p;
                rs += p;
            }
#pragma unroll
            for (int off = 8; off; off >>= 1)
                rs += __shfl_xor_sync(0xffffffffu, rs, off);
            l_i[i] = l_i[i] * alpha + rs;
#pragma unroll
            for (int j = 0; j < 4; j++) o[i][j] *= alpha;
            *reinterpret_cast<float4*>(&Ps[(ty * 4 + i) * 68 + tx * 4]) =
                make_float4(s4[i][0], s4[i][1], s4[i][2], s4[i][3]);
        }
        __syncthreads();

#pragma unroll
        for (int k4 = 0; k4 < 16; k4++) {
            float4 vf0 = *reinterpret_cast<const float4*>(&Vs[(k4 * 4 + 0) * 68 + tx * 4]);
            float4 vf1 = *reinterpret_cast<const float4*>(&Vs[(k4 * 4 + 1) * 68 + tx * 4]);
            float4 vf2 = *reinterpret_cast<const float4*>(&Vs[(k4 * 4 + 2) * 68 + tx * 4]);
            float4 vf3 = *reinterpret_cast<const float4*>(&Vs[(k4 * 4 + 3) * 68 + tx * 4]);
#pragma unroll
            for (int i = 0; i < 4; i++) {
                float4 pf = *reinterpret_cast<const float4*>(&Ps[(ty * 4 + i) * 68 + k4 * 4]);
                o[i][0] += pf.x * vf0.x + pf.y * vf1.x + pf.z * vf2.x + pf.w * vf3.x;
                o[i][1] += pf.x * vf0.y + pf.y * vf1.y + pf.z * vf2.y + pf.w * vf3.y;
                o[i][2] += pf.x * vf0.z + pf.y * vf1.z + pf.z * vf2.z + pf.w * vf3.z;
                o[i][3] += pf.x * vf0.w + pf.y * vf1.w + pf.z * vf2.w + pf.w * vf3.w;
            }
        }
    }

#pragma unroll
    for (int i = 0; i < 4; i++) {
        float inv = 1.0f / l_i[i];
        int qg = qt0 + ty * 4 + i;
        float4 out = make_float4(o[i][0] * inv, o[i][1] * inv,
                                 o[i][2] * inv, o[i][3] * inv);
        *reinterpret_cast<float4*>(
            &ctx[((size_t)(b * SQ_) + qg) * D_ + h * DK_ + tx * 4]) = out;
    }
}

static const int ATTN_SMEM = (4 * 64 * 68) * (int)sizeof(float) + 64 * (int)sizeof(int);

extern "C" void kernel_launch(void* const* d_in, const int* in_sizes, int n_in,
                              void* d_out, int out_size) {
    const float* query = (const float*)d_in[0];
    const float* keyi  = (const float*)d_in[1];
    const float* value = (const float*)d_in[2];
    const int*   mask  = (const int*)d_in[3];
    const float* Wq    = (const float*)d_in[4];
    const float* Wk    = (const float*)d_in[5];
    const float* Wv    = (const float*)d_in[6];
    const float* Wo    = (const float*)d_in[7];
    float* out = (float*)d_out;

    float *qb, *kb, *vb, *cb;
    __nv_bfloat16 *xhi, *xlo, *whi, *wlo;
    cudaGetSymbolAddress((void**)&qb, g_q);
    cudaGetSymbolAddress((void**)&kb, g_k);
    cudaGetSymbolAddress((void**)&vb, g_v);
    cudaGetSymbolAddress((void**)&cb, g_ctx);
    cudaGetSymbolAddress((void**)&xhi, g_xhi);
    cudaGetSymbolAddress((void**)&xlo, g_xlo);
    cudaGetSymbolAddress((void**)&whi, g_whi);
    cudaGetSymbolAddress((void**)&wlo, g_wlo);

    cudaFuncSetAttribute(attn_fwd, cudaFuncAttributeMaxDynamicSharedMemorySize,
                         ATTN_SMEM);
    cudaFuncSetAttribute(gemm_mma<0>, cudaFuncAttributeMaxDynamicSharedMemorySize,
                         GS_SMEM);
    cudaFuncSetAttribute(gemm_mma<1>, cudaFuncAttributeMaxDynamicSharedMemorySize,
                         GS_SMEM);

    const int NX4 = 4096 * 1024 / 4;
    const int NW4 = 1024 * 1024 / 4;
    dim3 gg(1024 / 128, 4096 / 128);  // (8, 32)

    // Q projection
    cvt_split<<<1024, 256>>>(query, xhi, xlo, NX4);
    cvt_split<<<512, 256>>>(Wq, whi, wlo, NW4);
    gemm_mma<1><<<gg, 256, GS_SMEM>>>(xhi, xlo, whi, wlo, qb);
    // K projection
    cvt_split<<<1024, 256>>>(keyi, xhi, xlo, NX4);
    cvt_split<<<512, 256>>>(Wk, whi, wlo, NW4);
    gemm_mma<1><<<gg, 256, GS_SMEM>>>(xhi, xlo, whi, wlo, kb);
    // V projection
    cvt_split<<<1024, 256>>>(value, xhi, xlo, NX4);
    cvt_split<<<512, 256>>>(Wv, whi, wlo, NW4);
    gemm_mma<1><<<gg, 256, GS_SMEM>>>(xhi, xlo, whi, wlo, vb);
    // attention
    attn_fwd<<<dim3(SQ_ / 64, B_ * H_), 256, ATTN_SMEM>>>(qb, kb, vb, mask, cb);
    // output projection
    cvt_split<<<1024, 256>>>(cb, xhi, xlo, NX4);
    cvt_split<<<512, 256>>>(Wo, whi, wlo, NW4);
    gemm_mma<0><<<gg, 256, GS_SMEM>>>(xhi, xlo, whi, wlo, out);
}

// round 14
// speedup vs baseline: 1.3160x; 1.0100x over previous
#include <cuda_runtime.h>
#include <cuda_bf16.h>
#include <cstdint>

#define B_   2
#define SQ_  2048
#define SK_  2048
#define D_   1024
#define H_   16
#define DK_  64

// ---------------------------------------------------------------------------
// Scratch (allocation-free: static device globals)
// ---------------------------------------------------------------------------
__device__ float g_q[(size_t)B_ * H_ * SQ_ * DK_];   // [B,H,SQ,DK]
__device__ float g_k[(size_t)B_ * H_ * SK_ * DK_];   // [B,H,SK,DK]
__device__ float g_v[(size_t)B_ * H_ * SK_ * DK_];   // [B,H,SK,DK]
__device__ float g_ctx[(size_t)B_ * SQ_ * D_];       // [B,SQ,D]

// split-bf16 staging buffers (reused sequentially across the 4 GEMMs)
__device__ __align__(16) __nv_bfloat16 g_xhi[(size_t)4096 * 1024];
__device__ __align__(16) __nv_bfloat16 g_xlo[(size_t)4096 * 1024];
__device__ __align__(16) __nv_bfloat16 g_whi[(size_t)1024 * 1024];
__device__ __align__(16) __nv_bfloat16 g_wlo[(size_t)1024 * 1024];

__device__ __forceinline__ float neg_inf() { return __int_as_float(0xff800000); }

__device__ __forceinline__ uint32_t smem_u32(const void* p) {
    uint32_t a;
    asm("{ .reg .u64 t; cvta.to.shared.u64 t, %1; cvt.u32.u64 %0, t; }"
        : "=r"(a) : "l"(p));
    return a;
}

// plain (non-transposed) ldmatrix x4 — correct for BOTH A[m][k] and W[n][k]
// since both are k-contiguous and the mma fragments want k-pairs.
__device__ __forceinline__ void ldm_x4(uint32_t* r, uint32_t addr) {
    asm volatile(
        "ldmatrix.sync.aligned.m8n8.x4.shared.b16 {%0,%1,%2,%3}, [%4];"
        : "=r"(r[0]), "=r"(r[1]), "=r"(r[2]), "=r"(r[3]) : "r"(addr));
}

__device__ __forceinline__ void mma_bf16(float* c, const uint32_t* a,
                                         uint32_t b0, uint32_t b1) {
    asm volatile(
        "mma.sync.aligned.m16n8k16.row.col.f32.bf16.bf16.f32 "
        "{%0,%1,%2,%3}, {%4,%5,%6,%7}, {%8,%9}, {%0,%1,%2,%3};"
        : "+f"(c[0]), "+f"(c[1]), "+f"(c[2]), "+f"(c[3])
        : "r"(a[0]), "r"(a[1]), "r"(a[2]), "r"(a[3]), "r"(b0), "r"(b1));
}

// ---------------------------------------------------------------------------
// fp32 -> (hi, lo) bf16 split.  x = hi + lo with |x - hi - lo| ~ 2^-17 |x|.
// ---------------------------------------------------------------------------
__global__ void cvt_split(const float* __restrict__ x,
                          __nv_bfloat16* __restrict__ hi,
                          __nv_bfloat16* __restrict__ lo, int n4) {
    int i = blockIdx.x * blockDim.x + threadIdx.x;
    int stride = gridDim.x * blockDim.x;
    for (; i < n4; i += stride) {
        float4 v = reinterpret_cast<const float4*>(x)[i];
        __nv_bfloat16 hx = __float2bfloat16(v.x);
        __nv_bfloat16 hy = __float2bfloat16(v.y);
        __nv_bfloat16 hz = __float2bfloat16(v.z);
        __nv_bfloat16 hw = __float2bfloat16(v.w);
        __nv_bfloat162* hp = reinterpret_cast<__nv_bfloat162*>(hi + (size_t)i * 4);
        hp[0] = __halves2bfloat162(hx, hy);
        hp[1] = __halves2bfloat162(hz, hw);
        float lx = v.x - __bfloat162float(hx);
        float ly = v.y - __bfloat162float(hy);
        float lz = v.z - __bfloat162float(hz);
        float lw = v.w - __bfloat162float(hw);
        __nv_bfloat162* lp = reinterpret_cast<__nv_bfloat162*>(lo + (size_t)i * 4);
        lp[0] = __halves2bfloat162(__float2bfloat16(lx), __float2bfloat16(ly));
        lp[1] = __halves2bfloat162(__float2bfloat16(lz), __float2bfloat16(lw));
    }
}

// ---------------------------------------------------------------------------
// split-bf16 MMA GEMM:  Y[M,N] = X[M,K] @ W[N,K]^T, M=4096, N=K=1024.
// 128x128 CTA tile, BK=32, double-buffered smem, 8 warps (64x32 warp tiles),
// mma.sync.m16n8k16 bf16 with fp32 accumulators.
// Per k16 step: 3 products (hi*hi, hi*lo, lo*hi) x 16 mma-tiles = 48 mma/warp.
// MODE 0: Y row-major.  MODE 1: Y scattered to [B,H,S,DK].
// ---------------------------------------------------------------------------
static constexpr int GS_ROW  = 40;                       // bf16 per smem row (32+8 pad)
static constexpr int GS_ARR  = 128 * GS_ROW * 2;         // 10240 B per operand tile
static constexpr int GS_BUF  = 4 * GS_ARR;               // Ahi,Alo,Bhi,Blo = 40960 B
static constexpr int GS_SMEM = 2 * GS_BUF;               // 81920 B

template <int MODE>
__global__ __launch_bounds__(256) void gemm_mma(const __nv_bfloat16* __restrict__ Ahi,
                                                const __nv_bfloat16* __restrict__ Alo,
                                                const __nv_bfloat16* __restrict__ Bhi,
                                                const __nv_bfloat16* __restrict__ Blo,
                                                float* __restrict__ Y) {
    extern __shared__ __align__(16) char sm[];
    const uint32_t sbase = smem_u32(sm);
    const int tid  = threadIdx.x;
    const int wid  = tid >> 5;
    const int lane = tid & 31;
    const int m0 = blockIdx.y * 128;
    const int n0 = blockIdx.x * 128;
    const int K  = 1024;

    const int wy = wid & 1;        // m half (0..1) -> 64 rows
    const int wx = wid >> 1;       // n quarter (0..3) -> 32 cols

    float c[4][4][4];
#pragma unroll
    for (int mt = 0; mt < 4; mt++)
#pragma unroll
        for (int nt = 0; nt < 4; nt++)
#pragma unroll
            for (int e = 0; e < 4; e++) c[mt][nt][e] = 0.f;

    // Fill one double-buffer slot with the 4 operand tiles at k0.
    auto load_buf = [&](int kt, int buf) {
        const int k0 = kt * 32;
        const char* srcs[4] = {(const char*)Ahi, (const char*)Alo,
                               (const char*)Bhi, (const char*)Blo};
#pragma unroll
        for (int a = 0; a < 4; a++) {
            const __nv_bfloat16* src = (const __nv_bfloat16*)srcs[a];
            const int row0 = (a < 2) ? m0 : n0;
            char* dst = sm + buf * GS_BUF + a * GS_ARR;
#pragma unroll
            for (int s = 0; s < 2; s++) {
                int idx = tid + s * 256;       // 0..511
                int r = idx >> 2;              // row 0..127
                int cc = idx & 3;              // 16B chunk (4 per 32-col row)
                uint4 v = *reinterpret_cast<const uint4*>(
                    &src[(size_t)(row0 + r) * K + k0 + cc * 8]);
                *reinterpret_cast<uint4*>(dst + r * (GS_ROW * 2) + cc * 16) = v;
            }
        }
    };

    load_buf(0, 0);
    __syncthreads();

    // ldmatrix lane addressing (identical formula for A and B, non-trans):
    // row = base + (lane & 15), col = ks + (lane >> 4) * 8
    const int lrow = lane & 15;
    const int lcol = (lane >> 4) * 8;

    const int NT = K / 32;  // 32
    for (int kt = 0; kt < NT; kt++) {
        const int buf = kt & 1;
        if (kt + 1 < NT) load_buf(kt + 1, buf ^ 1);  // overlaps mma below

        const uint32_t bufb = sbase + buf * GS_BUF;
        const uint32_t aoff_hi = bufb;
        const uint32_t aoff_lo = bufb + GS_ARR;
        const uint32_t boff_hi = bufb + 2 * GS_ARR;
        const uint32_t boff_lo = bufb + 3 * GS_ARR;

#pragma unroll
        for (int ks = 0; ks < 32; ks += 16) {
            uint32_t ahi[4][4], alo[4][4], bh[2][4], bl[2][4];
#pragma unroll
            for (int p = 0; p < 2; p++) {
                uint32_t off =
                    (uint32_t)((wx * 32 + p * 16 + lrow) * GS_ROW + ks + lcol) * 2;
                ldm_x4(bh[p], boff_hi + off);
                ldm_x4(bl[p], boff_lo + off);
            }
#pragma unroll
            for (int mt = 0; mt < 4; mt++) {
                uint32_t off =
                    (uint32_t)((wy * 64 + mt * 16 + lrow) * GS_ROW + ks + lcol) * 2;
                ldm_x4(ahi[mt], aoff_hi + off);
                ldm_x4(alo[mt], aoff_lo + off);
            }
            // b-fragments from x4 result: R0=b0(nt even), R1=b0(nt odd),
            //                             R2=b1(nt even), R3=b1(nt odd)
#pragma unroll
            for (int mt = 0; mt < 4; mt++)
#pragma unroll
                for (int nt = 0; nt < 4; nt++) {
                    int p = nt >> 1, sel = nt & 1;
                    mma_bf16(c[mt][nt], ahi[mt], bh[p][sel], bh[p][sel + 2]);
                }
#pragma unroll
            for (int mt = 0; mt < 4; mt++)
#pragma unroll
                for (int nt = 0; nt < 4; nt++) {
                    int p = nt >> 1, sel = nt & 1;
                    mma_bf16(c[mt][nt], ahi[mt], bl[p][sel], bl[p][sel + 2]);
                }
#pragma unroll
            for (int mt = 0; mt < 4; mt++)
#pragma unroll
                for (int nt = 0; nt < 4; nt++) {
                    int p = nt >> 1, sel = nt & 1;
                    mma_bf16(c[mt][nt], alo[mt], bh[p][sel], bh[p][sel + 2]);
                }
        }
        __syncthreads();
    }

    // Epilogue: c0,c1 at (row = lane>>2, col = (lane&3)*2); c2,c3 at row+8.
#pragma unroll
    for (int mt = 0; mt < 4; mt++) {
#pragma unroll
        for (int nt = 0; nt < 4; nt++) {
            int row = m0 + wy * 64 + mt * 16 + (lane >> 2);
            int col = n0 + wx * 32 + nt * 8 + (lane & 3) * 2;
#pragma unroll
            for (int half = 0; half < 2; half++) {
                int m = row + half * 8;
                float2 v = make_float2(c[mt][nt][half * 2 + 0],
                                       c[mt][nt][half * 2 + 1]);
                if (MODE == 0) {
                    *reinterpret_cast<float2*>(&Y[(size_t)m * 1024 + col]) = v;
                } else {
                    int h  = col >> 6;
                    int dk = col & 63;
                    int b  = m >> 11;
                    int s  = m & 2047;
                    *reinterpret_cast<float2*>(
                        &Y[(((size_t)(b * H_ + h)) * SQ_ + s) * DK_ + dk]) = v;
                }
            }
        }
    }
}

// ---------------------------------------------------------------------------
// Flash attention, fp32, causal + padding mask (unchanged from R6 best).
// ---------------------------------------------------------------------------
__global__ __launch_bounds__(256) void attn_fwd(const float* __restrict__ Qp,
                                                const float* __restrict__ Kp,
                                                const float* __restrict__ Vp,
                                                const int* __restrict__ mask,
                                                float* __restrict__ ctx) {
    extern __shared__ float smf[];
    float* Qst = smf;
    float* Kst = Qst + 64 * 68;
    float* Vs  = Kst + 64 * 68;
    float* Ps  = Vs  + 64 * 68;
    int*   mS  = (int*)(Ps + 64 * 68);

    const int tid = threadIdx.x;
    const int tx = tid & 15;
    const int ty = tid >> 4;
    const int qt0 = blockIdx.x * 64;
    const int bh  = blockIdx.y;
    const int b   = bh >> 4;
    const int h   = bh & 15;

    const float* Qb = Qp + (size_t)bh * SQ_ * DK_;
    const float* Kb = Kp + (size_t)bh * SK_ * DK_;
    const float* Vb = Vp + (size_t)bh * SK_ * DK_;
    const int*   mb = mask + b * SK_;

#pragma unroll
    for (int s = 0; s < 4; s++) {
        int slot = tid + s * 256;
        int r  = slot >> 4;
        int c4 = (slot & 15) * 4;
        float4 v = *reinterpret_cast<const float4*>(&Qb[(size_t)(qt0 + r) * DK_ + c4]);
        Qst[(c4 + 0) * 68 + r] = v.x; Qst[(c4 + 1) * 68 + r] = v.y;
        Qst[(c4 + 2) * 68 + r] = v.z; Qst[(c4 + 3) * 68 + r] = v.w;
    }

    float m_i[4], l_i[4], o[4][4];
#pragma unroll
    for (int i = 0; i < 4; i++) {
        m_i[i] = neg_inf();
        l_i[i] = 0.f;
#pragma unroll
        for (int j = 0; j < 4; j++) o[i][j] = 0.f;
    }

    const int ktMax = qt0 >> 6;
    for (int kt = 0; kt <= ktMax; kt++) {
        const int kt0 = kt * 64;
        if (mb[kt0] == 0) break;

        __syncthreads();
        if (tid < 64) mS[tid] = mb[kt0 + tid];
#pragma unroll
        for (int s = 0; s < 4; s++) {
            int slot = tid + s * 256;
            int r  = slot >> 4;
            int c4 = (slot & 15) * 4;
            float4 kv = *reinterpret_cast<const float4*>(&Kb[(size_t)(kt0 + r) * DK_ + c4]);
            Kst[(c4 + 0) * 68 + r] = kv.x; Kst[(c4 + 1) * 68 + r] = kv.y;
            Kst[(c4 + 2) * 68 + r] = kv.z; Kst[(c4 + 3) * 68 + r] = kv.w;
            float4 vv = *reinterpret_cast<const float4*>(&Vb[(size_t)(kt0 + r) * DK_ + c4]);
            *reinterpret_cast<float4*>(&Vs[r * 68 + c4]) = vv;
        }
        __syncthreads();

        float s4[4][4];
#pragma unroll
        for (int i = 0; i < 4; i++)
#pragma unroll
            for (int j = 0; j < 4; j++) s4[i][j] = 0.f;

#pragma unroll 16
        for (int kk = 0; kk < 64; kk++) {
            float4 qf = *reinterpret_cast<const float4*>(&Qst[kk * 68 + ty * 4]);
            float4 kf = *reinterpret_cast<const float4*>(&Kst[kk * 68 + tx * 4]);
            float qa[4] = {qf.x, qf.y, qf.z, qf.w};
            float ka[4] = {kf.x, kf.y, kf.z, kf.w};
#pragma unroll
            for (int i = 0; i < 4; i++)
#pragma unroll
                for (int j = 0; j < 4; j++)
                    s4[i][j] = fmaf(qa[i], ka[j], s4[i][j]);
        }

#pragma unroll
        for (int i = 0; i < 4; i++) {
            int qg = qt0 + ty * 4 + i;
            float mt = neg_inf();
#pragma unroll
            for (int j = 0; j < 4; j++) {
                int kg = kt0 + tx * 4 + j;
                float v = s4[i][j] * 0.125f;
                if (kg > qg || mS[tx * 4 + j] == 0) v = neg_inf();
                s4[i][j] = v;
                mt = fmaxf(mt, v);
            }
#pragma unroll
            for (int off = 8; off; off >>= 1)
                mt = fmaxf(mt, __shfl_xor_sync(0xffffffffu, mt, off));
            float mnew  = fmaxf(m_i[i], mt);
            float alpha = __expf(m_i[i] - mnew);
            m_i[i] = mnew;
            float rs = 0.f;
#pragma unroll
            for (int j = 0; j < 4; j++) {
                float p = __expf(s4[i][j] - mnew);
                s4[i][j] = p;
                rs += p;
            }
#pragma unroll
            for (int off = 8; off; off >>= 1)
                rs += __shfl_xor_sync(0xffffffffu, rs, off);
            l_i[i] = l_i[i] * alpha + rs;
#pragma unroll
            for (int j = 0; j < 4; j++) o[i][j] *= alpha;
            *reinterpret_cast<float4*>(&Ps[(ty * 4 + i) * 68 + tx * 4]) =
                make_float4(s4[i][0], s4[i][1], s4[i][2], s4[i][3]);
        }
        __syncthreads();

#pragma unroll
        for (int k4 = 0; k4 < 16; k4++) {
            float4 vf0 = *reinterpret_cast<const float4*>(&Vs[(k4 * 4 + 0) * 68 + tx * 4]);
            float4 vf1 = *reinterpret_cast<const float4*>(&Vs[(k4 * 4 + 1) * 68 + tx * 4]);
            float4 vf2 = *reinterpret_cast<const float4*>(&Vs[(k4 * 4 + 2) * 68 + tx * 4]);
            float4 vf3 = *reinterpret_cast<const float4*>(&Vs[(k4 * 4 + 3) * 68 + tx * 4]);
#pragma unroll
            for (int i = 0; i < 4; i++) {
                float4 pf = *reinterpret_cast<const float4*>(&Ps[(ty * 4 + i) * 68 + k4 * 4]);
                o[i][0] += pf.x * vf0.x + pf.y * vf1.x + pf.z * vf2.x + pf.w * vf3.x;
                o[i][1] += pf.x * vf0.y + pf.y * vf1.y + pf.z * vf2.y + pf.w * vf3.y;
                o[i][2] += pf.x * vf0.z + pf.y * vf1.z + pf.z * vf2.z + pf.w * vf3.z;
                o[i][3] += pf.x * vf0.w + pf.y * vf1.w + pf.z * vf2.w + pf.w * vf3.w;
            }
        }
    }

#pragma unroll
    for (int i = 0; i < 4; i++) {
        float inv = 1.0f / l_i[i];
        int qg = qt0 + ty * 4 + i;
        float4 out = make_float4(o[i][0] * inv, o[i][1] * inv,
                                 o[i][2] * inv, o[i][3] * inv);
        *reinterpret_cast<float4*>(
            &ctx[((size_t)(b * SQ_) + qg) * D_ + h * DK_ + tx * 4]) = out;
    }
}

static const int ATTN_SMEM = (4 * 64 * 68) * (int)sizeof(float) + 64 * (int)sizeof(int);

extern "C" void kernel_launch(void* const* d_in, const int* in_sizes, int n_in,
                              void* d_out, int out_size) {
    const float* query = (const float*)d_in[0];
    const float* keyi  = (const float*)d_in[1];
    const float* value = (const float*)d_in[2];
    const int*   mask  = (const int*)d_in[3];
    const float* Wq    = (const float*)d_in[4];
    const float* Wk    = (const float*)d_in[5];
    const float* Wv    = (const float*)d_in[6];
    const float* Wo    = (const float*)d_in[7];
    float* out = (float*)d_out;

    float *qb, *kb, *vb, *cb;
    __nv_bfloat16 *xhi, *xlo, *whi, *wlo;
    cudaGetSymbolAddress((void**)&qb, g_q);
    cudaGetSymbolAddress((void**)&kb, g_k);
    cudaGetSymbolAddress((void**)&vb, g_v);
    cudaGetSymbolAddress((void**)&cb, g_ctx);
    cudaGetSymbolAddress((void**)&xhi, g_xhi);
    cudaGetSymbolAddress((void**)&xlo, g_xlo);
    cudaGetSymbolAddress((void**)&whi, g_whi);
    cudaGetSymbolAddress((void**)&wlo, g_wlo);

    cudaFuncSetAttribute(attn_fwd, cudaFuncAttributeMaxDynamicSharedMemorySize,
                         ATTN_SMEM);
    cudaFuncSetAttribute(gemm_mma<0>, cudaFuncAttributeMaxDynamicSharedMemorySize,
                         GS_SMEM);
    cudaFuncSetAttribute(gemm_mma<1>, cudaFuncAttributeMaxDynamicSharedMemorySize,
                         GS_SMEM);

    const int NX4 = 4096 * 1024 / 4;
    const int NW4 = 1024 * 1024 / 4;
    dim3 gg(1024 / 128, 4096 / 128);  // (8, 32)

    // Q projection
    cvt_split<<<1024, 256>>>(query, xhi, xlo, NX4);
    cvt_split<<<512, 256>>>(Wq, whi, wlo, NW4);
    gemm_mma<1><<<gg, 256, GS_SMEM>>>(xhi, xlo, whi, wlo, qb);
    // K projection
    cvt_split<<<1024, 256>>>(keyi, xhi, xlo, NX4);
    cvt_split<<<512, 256>>>(Wk, whi, wlo, NW4);
    gemm_mma<1><<<gg, 256, GS_SMEM>>>(xhi, xlo, whi, wlo, kb);
    // V projection
    cvt_split<<<1024, 256>>>(value, xhi, xlo, NX4);
    cvt_split<<<512, 256>>>(Wv, whi, wlo, NW4);
    gemm_mma<1><<<gg, 256, GS_SMEM>>>(xhi, xlo, whi, wlo, vb);
    // attention
    attn_fwd<<<dim3(SQ_ / 64, B_ * H_), 256, ATTN_SMEM>>>(qb, kb, vb, mask, cb);
    // output projection
    cvt_split<<<1024, 256>>>(cb, xhi, xlo, NX4);
    cvt_split<<<512, 256>>>(Wo, whi, wlo, NW4);
    gemm_mma<0><<<gg, 256, GS_SMEM>>>(xhi, xlo, whi, wlo, out);
}